// round 12
// baseline (speedup 1.0000x reference)
#include <cuda_runtime.h>
#include <cuda_bf16.h>
#include <cuda_fp16.h>
#include <stdint.h>

#define NN 50000
#define NE 800000
#define INF 128
#define HID 64
#define S ((size_t)NN * HID)

// packed dual fp32 FMA (sm_103a)
#define FMA_F32X2(d, a, b, c) \
    asm("fma.rn.f32x2 %0, %1, %2, %3;" : "=l"(d) : "l"(a), "l"(b), "l"(c))

__device__ __forceinline__ float x2lo(unsigned long long v) {
    return __uint_as_float((unsigned)(v & 0xffffffffull));
}
__device__ __forceinline__ float x2hi(unsigned long long v) {
    return __uint_as_float((unsigned)(v >> 32));
}

// ---------------- scratch ----------------
// fbuf slots: 0=fo0 1=fs0 2=fo1 3=fs1
__device__ float d_fbuf[(size_t)4 * NN * HID];
__device__ __align__(16) __half d_gh[(size_t)4 * NN * HID];
__device__ float d_dinv[2 * NN];
__device__ int   d_cnt [2 * NN];
__device__ int   d_cur [2 * NN];
__device__ int   d_rs  [2 * (NN + 1)];
__device__ int   d_csr [2 * NE];
__device__ float d_weff[16384];   // tail layer-1 weights [s(4)][kp(32)][c(64)][2]

// ---------------- degree histogram ----------------
__global__ void count_k(const int4* __restrict__ d0, const int4* __restrict__ d1,
                        int* __restrict__ cnt, int ne4) {
    int i = blockIdx.x * blockDim.x + threadIdx.x;
    if (i >= 2 * ne4) return;
    int b = (i >= ne4) ? 1 : 0;
    int4 v = b ? d1[i - ne4] : d0[i];
    int* c = cnt + b * NN;
    atomicAdd(&c[v.x], 1);
    atomicAdd(&c[v.y], 1);
    atomicAdd(&c[v.z], 1);
    atomicAdd(&c[v.w], 1);
}

// ---------------- exclusive scan + dinv + cur init ----------------
__global__ void scan_k(const int* __restrict__ cntA, int* __restrict__ rsA,
                       float* __restrict__ dvA, int* __restrict__ curA, int n) {
    const int* cnt = cntA + blockIdx.x * NN;
    int*       rs  = rsA  + blockIdx.x * (NN + 1);
    float*     dv  = dvA  + blockIdx.x * NN;
    int*       cur = curA + blockIdx.x * NN;
    __shared__ int wsum[32];
    __shared__ int carry_s;
    int tid = threadIdx.x, lane = tid & 31, wid = tid >> 5;
    if (tid == 0) carry_s = 0;
    __syncthreads();
    for (int base = 0; base < n; base += 1024) {
        int i = base + tid;
        int v = (i < n) ? cnt[i] : 0;
        int x = v;
        #pragma unroll
        for (int d = 1; d < 32; d <<= 1) {
            int t = __shfl_up_sync(0xffffffffu, x, d);
            if (lane >= d) x += t;
        }
        if (lane == 31) wsum[wid] = x;
        __syncthreads();
        if (wid == 0) {
            int w = wsum[lane];
            int y = w;
            #pragma unroll
            for (int d = 1; d < 32; d <<= 1) {
                int t = __shfl_up_sync(0xffffffffu, y, d);
                if (lane >= d) y += t;
            }
            wsum[lane] = y - w;
        }
        __syncthreads();
        int excl = x - v + wsum[wid] + carry_s;
        if (i < n) {
            rs[i]  = excl;
            cur[i] = excl;
            dv[i]  = rsqrtf((float)(v > 0 ? v : 1));
        }
        __syncthreads();
        if (tid == 1023) carry_s = excl + v;
        __syncthreads();
    }
    if (threadIdx.x == 0) rs[n] = carry_s;
}

// ---------------- CSR fill ----------------
__global__ void fill_k(const int4* __restrict__ s0, const int4* __restrict__ s1,
                       const int4* __restrict__ d0, const int4* __restrict__ d1,
                       int* __restrict__ cur, int* __restrict__ csr, int ne4) {
    int i = blockIdx.x * blockDim.x + threadIdx.x;
    if (i >= 2 * ne4) return;
    int b = (i >= ne4) ? 1 : 0;
    int j = i - b * ne4;
    int4 dd = b ? d1[j] : d0[j];
    int4 sv = b ? s1[j] : s0[j];
    int* cu = cur + b * NN;
    int* cs = csr + (size_t)b * NE;
    cs[atomicAdd(&cu[dd.x], 1)] = sv.x;
    cs[atomicAdd(&cu[dd.y], 1)] = sv.y;
    cs[atomicAdd(&cu[dd.z], 1)] = sv.z;
    cs[atomicAdd(&cu[dd.w], 1)] = sv.w;
}

// ---------------- input GEMM + relu (reg-capped for 4 CTAs/SM) ----------------
__global__ void __launch_bounds__(256, 4) gemm_relu_k(
        const float* __restrict__ X0, const float* __restrict__ X1,
        const float* __restrict__ W0g, const float* __restrict__ W1g,
        const float* __restrict__ b0, const float* __restrict__ b1,
        float* __restrict__ f0base, int n) {
    __shared__ float Xs[64 * 64];    // 16 KB (one 64-k chunk)
    __shared__ float Wpc[4096];      // 16 KB [32kp][64c][2]
    int by = blockIdx.y;
    const float* X = by ? X1 : X0;
    const float* W = by ? W1g : W0g;
    const float* b = by ? b1 : b0;
    float* H = f0base + (size_t)by * S;

    int tid = threadIdx.x;
    int cp = tid & 15;
    int ng = tid >> 4;        // 0..15, 4 nodes each
    int nb = blockIdx.x * 64;
    int nvalid = n - nb; if (nvalid > 64) nvalid = 64;

    unsigned long long acc[4][4];
    #pragma unroll
    for (int j = 0; j < 4; j++)
        #pragma unroll
        for (int q = 0; q < 4; q++) acc[j][q] = 0ull;

    #pragma unroll
    for (int ch = 0; ch < 2; ch++) {
        __syncthreads();
        for (int i4 = tid; i4 < 1024; i4 += 256) {
            int node = i4 >> 4, f = i4 & 15;
            float4 v = make_float4(0.f, 0.f, 0.f, 0.f);
            if (node < nvalid)
                v = *(const float4*)(X + (size_t)(nb + node) * 128 + ch * 64 + f * 4);
            ((float4*)Xs)[i4] = v;
        }
        for (int i = tid; i < 4096; i += 256) {
            int j = i & 1, c = (i >> 1) & 63, kp = i >> 7;
            Wpc[i] = W[(size_t)(ch * 64 + 2 * kp + j) * 64 + c];
        }
        __syncthreads();
        #pragma unroll 4
        for (int kp2 = 0; kp2 < 16; kp2++) {
            float4 x4[4];
            #pragma unroll
            for (int j = 0; j < 4; j++)
                x4[j] = *(const float4*)&Xs[(ng * 4 + j) * 64 + 4 * kp2];
            #pragma unroll
            for (int h = 0; h < 2; h++) {
                int kp = 2 * kp2 + h;
                unsigned long long w[4];
                #pragma unroll
                for (int q = 0; q < 4; q++)
                    w[q] = *(const unsigned long long*)&Wpc[(kp * 64 + cp + 16 * q) * 2];
                #pragma unroll
                for (int j = 0; j < 4; j++) {
                    unsigned long long x = ((const unsigned long long*)&x4[j])[h];
                    #pragma unroll
                    for (int q = 0; q < 4; q++) FMA_F32X2(acc[j][q], x, w[q], acc[j][q]);
                }
            }
        }
    }

    #pragma unroll
    for (int j = 0; j < 4; j++) {
        int node = nb + ng * 4 + j;
        if (node < n) {
            #pragma unroll
            for (int q = 0; q < 4; q++) {
                int col = cp + 16 * q;
                float v = x2lo(acc[j][q]) + x2hi(acc[j][q]) + b[col];
                H[(size_t)node * 64 + col] = v > 0.f ? v : 0.f;
            }
        }
    }
}

// ---------------- g(fp16) = H * dinv ----------------
__global__ void scale_k(const float4* __restrict__ H, const float* __restrict__ dinv_all,
                        uint4* __restrict__ G, int total) {
    int i = blockIdx.x * blockDim.x + threadIdx.x;
    if (i >= total) return;
    float dv = dinv_all[i >> 3];
    float4 a = H[2 * i], b = H[2 * i + 1];
    __half2 h0 = __floats2half2_rn(a.x * dv, a.y * dv);
    __half2 h1 = __floats2half2_rn(a.z * dv, a.w * dv);
    __half2 h2 = __floats2half2_rn(b.x * dv, b.y * dv);
    __half2 h3 = __floats2half2_rn(b.z * dv, b.w * dv);
    uint4 o;
    o.x = *(unsigned*)&h0; o.y = *(unsigned*)&h1;
    o.z = *(unsigned*)&h2; o.w = *(unsigned*)&h3;
    G[i] = o;
}

// ---------------- tail weight prep: [s][kp][c][2]; s=0..2 -> Wm1 block s, s=3 -> sum(3,4,5)
__global__ void prep_k(const float* __restrict__ Wm1, float* __restrict__ weff) {
    int i = blockIdx.x * blockDim.x + threadIdx.x;
    if (i >= 16384) return;
    int j = i & 1, c = (i >> 1) & 63, kpg = i >> 7;  // kpg 0..127
    int s = kpg >> 5;
    int kk = 2 * (kpg & 31) + j;                     // 0..63 within segment
    float v;
    if (s < 3)
        v = Wm1[(s * 64 + kk) * 64 + c];
    else
        v = Wm1[(192 + kk) * 64 + c] + Wm1[(256 + kk) * 64 + c] +
            Wm1[(320 + kk) * 64 + c];
    weff[i] = v;
}

// ---------------- prop step 1: f1 = f0 - dinv*gather(ga); g1 = f1*dinv ----------------
__global__ void prop_k(const __half* __restrict__ gin, const float* __restrict__ fin,
                       float* __restrict__ fout, __half* __restrict__ gout,
                       const float* __restrict__ dinv_all, const int* __restrict__ rs_all,
                       const int* __restrict__ csr_all, int n) {
    int gw = (blockIdx.x * blockDim.x + threadIdx.x) >> 5;
    int lane = threadIdx.x & 31;
    if (gw >= 2 * n) return;
    int b = (gw >= n) ? 1 : 0;
    int w = gw - b * n;
    const __half* gp  = gin + (size_t)b * S;
    const int*    rs  = rs_all + b * (NN + 1);
    const int*    csr = csr_all + (size_t)b * NE;
    int beg = rs[w], end = rs[w + 1];

    int grp = lane >> 3;
    int sub = lane & 7;

    float a[8];
    #pragma unroll
    for (int i = 0; i < 8; i++) a[i] = 0.f;

    for (int base = beg; base < end; base += 32) {
        int idx = base + lane;
        int sreg = (idx < end) ? __ldg(&csr[idx]) : 0;
        int cnt = end - base;
        if (cnt > 32) cnt = 32;
        #pragma unroll
        for (int tb = 0; tb < 8; tb++) {
            if (tb * 4 >= cnt) break;
            int t = tb * 4 + grp;
            int ss = __shfl_sync(0xffffffffu, sreg, t);
            if (t < cnt) {
                uint4 v = *(const uint4*)(gp + (size_t)ss * 64 + sub * 8);
                const __half2* h = (const __half2*)&v;
                #pragma unroll
                for (int q = 0; q < 4; q++) {
                    float2 f = __half22float2(h[q]);
                    a[2 * q]     += f.x;
                    a[2 * q + 1] += f.y;
                }
            }
        }
    }

    #pragma unroll
    for (int i = 0; i < 8; i++) {
        a[i] += __shfl_xor_sync(0xffffffffu, a[i], 8);
        a[i] += __shfl_xor_sync(0xffffffffu, a[i], 16);
    }

    if (lane < 8) {
        float dvv = dinv_all[b * NN + w];
        const float4* f4 = (const float4*)(fin + (size_t)b * S + (size_t)w * 64 + lane * 8);
        float4 fv0 = f4[0], fv1 = f4[1];
        float4 o0, o1;
        o0.x = fv0.x - a[0] * dvv;
        o0.y = fv0.y - a[1] * dvv;
        o0.z = fv0.z - a[2] * dvv;
        o0.w = fv0.w - a[3] * dvv;
        o1.x = fv1.x - a[4] * dvv;
        o1.y = fv1.y - a[5] * dvv;
        o1.z = fv1.z - a[6] * dvv;
        o1.w = fv1.w - a[7] * dvv;
        float4* fo = (float4*)(fout + (size_t)b * S + (size_t)w * 64 + lane * 8);
        fo[0] = o0;
        fo[1] = o1;
        __half2 h0 = __floats2half2_rn(o0.x * dvv, o0.y * dvv);
        __half2 h1 = __floats2half2_rn(o0.z * dvv, o0.w * dvv);
        __half2 h2 = __floats2half2_rn(o1.x * dvv, o1.y * dvv);
        __half2 h3 = __floats2half2_rn(o1.z * dvv, o1.w * dvv);
        uint4 gv;
        gv.x = *(unsigned*)&h0; gv.y = *(unsigned*)&h1;
        gv.z = *(unsigned*)&h2; gv.w = *(unsigned*)&h3;
        *(uint4*)(gout + (size_t)b * S + (size_t)w * 64 + lane * 8) = gv;
    }
}

// ---------------- prop step 2 + combine: write h_all directly ----------------
// f2 = f1 - dinv*gather(gb).  branch o (b=0): segs 0..2; branch s (b=1): segs 3..5.
__global__ void prop2h_k(const __half* __restrict__ gin, const float* __restrict__ f1base,
                         const float* __restrict__ f0base,
                         const float* __restrict__ dinv_all, const int* __restrict__ rs_all,
                         const int* __restrict__ csr_all, float* __restrict__ out, int n) {
    int gw = (blockIdx.x * blockDim.x + threadIdx.x) >> 5;
    int lane = threadIdx.x & 31;
    if (gw >= 2 * n) return;
    int b = (gw >= n) ? 1 : 0;
    int w = gw - b * n;
    const __half* gp  = gin + (size_t)b * S;
    const int*    rs  = rs_all + b * (NN + 1);
    const int*    csr = csr_all + (size_t)b * NE;
    int beg = rs[w], end = rs[w + 1];

    int grp = lane >> 3;
    int sub = lane & 7;

    float a[8];
    #pragma unroll
    for (int i = 0; i < 8; i++) a[i] = 0.f;

    for (int base = beg; base < end; base += 32) {
        int idx = base + lane;
        int sreg = (idx < end) ? __ldg(&csr[idx]) : 0;
        int cnt = end - base;
        if (cnt > 32) cnt = 32;
        #pragma unroll
        for (int tb = 0; tb < 8; tb++) {
            if (tb * 4 >= cnt) break;
            int t = tb * 4 + grp;
            int ss = __shfl_sync(0xffffffffu, sreg, t);
            if (t < cnt) {
                uint4 v = *(const uint4*)(gp + (size_t)ss * 64 + sub * 8);
                const __half2* h = (const __half2*)&v;
                #pragma unroll
                for (int q = 0; q < 4; q++) {
                    float2 f = __half22float2(h[q]);
                    a[2 * q]     += f.x;
                    a[2 * q + 1] += f.y;
                }
            }
        }
    }

    #pragma unroll
    for (int i = 0; i < 8; i++) {
        a[i] += __shfl_xor_sync(0xffffffffu, a[i], 8);
        a[i] += __shfl_xor_sync(0xffffffffu, a[i], 16);
    }

    if (lane < 8) {
        float dvv = dinv_all[b * NN + w];
        size_t roff = (size_t)b * S + (size_t)w * 64 + lane * 8;
        const float4* f14 = (const float4*)(f1base + roff);
        const float4* f04 = (const float4*)(f0base + roff);
        float4 f1v[2] = {f14[0], f14[1]};
        float4 f0v[2] = {f04[0], f04[1]};
        float* op = out + (size_t)w * 384 + lane * 8;
        #pragma unroll
        for (int h = 0; h < 2; h++) {
            float f2v[4];
            const float* f1p = (const float*)&f1v[h];
            const float* f0p = (const float*)&f0v[h];
            #pragma unroll
            for (int q = 0; q < 4; q++) f2v[q] = f1p[q] - a[4 * h + q] * dvv;
            float4 s0, s1, s2;
            if (b == 0) {
                #pragma unroll
                for (int q = 0; q < 4; q++) {
                    ((float*)&s0)[q] = 3.f * f0p[q] - 3.f * f1p[q] + 0.75f * f2v[q];
                    ((float*)&s1)[q] = 3.f * f1p[q] - 1.5f * f2v[q];
                    ((float*)&s2)[q] = 0.75f * f2v[q];
                }
                *(float4*)(op + h * 4)       = s0;
                *(float4*)(op + 64 + h * 4)  = s1;
                *(float4*)(op + 128 + h * 4) = s2;
            } else {
                #pragma unroll
                for (int q = 0; q < 4; q++)
                    ((float*)&s0)[q] = 4.f * (f0p[q] + f1p[q] + f2v[q]);
                *(float4*)(op + 192 + h * 4) = s0;
                *(float4*)(op + 256 + h * 4) = s0;
                *(float4*)(op + 320 + h * 4) = s0;
            }
        }
    }
}

// ---------------- tail MLP: reads h_all segs 0..3, writes logits ----------------
// 32 nodes/block, 256 thr; thread: 2 nodes x 4 cols.
__global__ void __launch_bounds__(256) tail_k(
        const float* __restrict__ hall, const float* __restrict__ weffp,
        const float* __restrict__ bm1, const float* __restrict__ Wm2,
        const float* __restrict__ bm2, float* __restrict__ logits, int n) {
    __shared__ float Xs[4][32 * 64];   // 32 KB
    __shared__ float Wpc[4096];        // 16 KB
    __shared__ float Zs[32 * 68];      // 8.5 KB
    int tid = threadIdx.x;
    int cp = tid & 15, ng = tid >> 4;
    int nb = blockIdx.x * 32;

    for (int t = tid; t < 2048; t += 256) {
        int s = t >> 9;
        int i4 = t & 511;
        int node = i4 >> 4, f = i4 & 15;
        float4 v = make_float4(0.f, 0.f, 0.f, 0.f);
        if (nb + node < n)
            v = *(const float4*)(hall + (size_t)(nb + node) * 384 + s * 64 + f * 4);
        ((float4*)Xs[s])[i4] = v;
    }

    unsigned long long acc[2][4];
    #pragma unroll
    for (int j = 0; j < 2; j++)
        #pragma unroll
        for (int q = 0; q < 4; q++) acc[j][q] = 0ull;

    #pragma unroll
    for (int s = 0; s < 4; s++) {
        __syncthreads();
        for (int i = tid; i < 4096; i += 256) Wpc[i] = weffp[s * 4096 + i];
        __syncthreads();
        #pragma unroll 4
        for (int kp2 = 0; kp2 < 16; kp2++) {
            float4 x4[2];
            #pragma unroll
            for (int j = 0; j < 2; j++)
                x4[j] = *(const float4*)&Xs[s][(ng * 2 + j) * 64 + 4 * kp2];
            #pragma unroll
            for (int h = 0; h < 2; h++) {
                int kp = 2 * kp2 + h;
                unsigned long long w[4];
                #pragma unroll
                for (int q = 0; q < 4; q++)
                    w[q] = *(const unsigned long long*)&Wpc[(kp * 64 + cp + 16 * q) * 2];
                #pragma unroll
                for (int j = 0; j < 2; j++) {
                    unsigned long long x = ((const unsigned long long*)&x4[j])[h];
                    #pragma unroll
                    for (int q = 0; q < 4; q++) FMA_F32X2(acc[j][q], x, w[q], acc[j][q]);
                }
            }
        }
    }
    __syncthreads();
    #pragma unroll
    for (int j = 0; j < 2; j++) {
        int node_l = ng * 2 + j;
        #pragma unroll
        for (int q = 0; q < 4; q++) {
            int col = cp + 16 * q;
            float z = x2lo(acc[j][q]) + x2hi(acc[j][q]) + bm1[col];
            Zs[node_l * 68 + col] = z > 0.f ? z : 0.f;
        }
    }
    __syncthreads();

    if (tid < 64) {
        int node = tid >> 1, jj = tid & 1;
        if (nb + node < n) {
            float sacc = bm2[jj];
            #pragma unroll 8
            for (int c = 0; c < 64; c++) sacc += Zs[node * 68 + c] * Wm2[c * 2 + jj];
            logits[(size_t)(nb + node) * 2 + jj] = sacc;
        }
    }
}

// ---------------- launch ----------------
extern "C" void kernel_launch(void* const* d_in, const int* in_sizes, int n_in,
                              void* d_out, int out_size) {
    const float* x     = (const float*)d_in[0];
    const float* sim_x = (const float*)d_in[1];
    const int*   src   = (const int*)d_in[2];
    const int*   dst   = (const int*)d_in[3];
    const int*   ssrc  = (const int*)d_in[4];
    const int*   sdst  = (const int*)d_in[5];
    const float* W1o   = (const float*)d_in[6];
    const float* b1o   = (const float*)d_in[7];
    const float* W1s   = (const float*)d_in[8];
    const float* b1s   = (const float*)d_in[9];
    const float* Wm1   = (const float*)d_in[10];
    const float* bm1   = (const float*)d_in[11];
    const float* Wm2   = (const float*)d_in[12];
    const float* bm2   = (const float*)d_in[13];

    const int n = NN, ne = NE;

    float *fbuf, *dinv, *weff; __half* gh; int *cnt, *cur, *rs, *csr;
    cudaGetSymbolAddress((void**)&fbuf, d_fbuf);
    cudaGetSymbolAddress((void**)&gh,   d_gh);
    cudaGetSymbolAddress((void**)&dinv, d_dinv);
    cudaGetSymbolAddress((void**)&cnt,  d_cnt);
    cudaGetSymbolAddress((void**)&cur,  d_cur);
    cudaGetSymbolAddress((void**)&rs,   d_rs);
    cudaGetSymbolAddress((void**)&csr,  d_csr);
    cudaGetSymbolAddress((void**)&weff, d_weff);

    float*  f0base = fbuf + 0 * S;
    float*  f1base = fbuf + 2 * S;
    __half* gabase = gh;
    __half* gbbase = gh + 2 * S;

    static cudaStream_t sB = nullptr;
    static cudaEvent_t eStart = nullptr, eScan = nullptr, eB = nullptr;
    if (!sB) {
        cudaStreamCreateWithFlags(&sB, cudaStreamNonBlocking);
        cudaEventCreateWithFlags(&eStart, cudaEventDisableTiming);
        cudaEventCreateWithFlags(&eScan,  cudaEventDisableTiming);
        cudaEventCreateWithFlags(&eB,     cudaEventDisableTiming);
    }

    cudaEventRecord(eStart, 0);
    cudaStreamWaitEvent(sB, eStart, 0);

    // stream0: CSR build chain
    cudaMemsetAsync(cnt, 0, (size_t)2 * NN * sizeof(int), 0);
    int ne4 = ne / 4;
    int eb4 = (2 * ne4 + 255) / 256;
    count_k<<<eb4, 256>>>((const int4*)dst, (const int4*)sdst, cnt, ne4);
    scan_k<<<2, 1024>>>(cnt, rs, dinv, cur, n);
    cudaEventRecord(eScan, 0);
    fill_k<<<eb4, 256>>>((const int4*)src, (const int4*)ssrc,
                         (const int4*)dst, (const int4*)sdst, cur, csr, ne4);

    // sB: gemm from t0 (input-only deps), prep, then scale after scan
    dim3 gg((n + 63) / 64, 2);
    gemm_relu_k<<<gg, 256, 0, sB>>>(x, sim_x, W1o, W1s, b1o, b1s, f0base, n);
    prep_k<<<64, 256, 0, sB>>>(Wm1, weff);
    cudaStreamWaitEvent(sB, eScan, 0);
    int total8 = (int)(2 * S / 8);
    scale_k<<<(total8 + 255) / 256, 256, 0, sB>>>((const float4*)f0base, dinv,
                                                  (uint4*)gabase, total8);
    cudaEventRecord(eB, sB);

    // join, then props + tail on stream0
    cudaStreamWaitEvent(0, eB, 0);
    float* out    = (float*)d_out;
    float* logits = out + (size_t)n * 384;
    int pb = (2 * n * 32 + 255) / 256;
    prop_k<<<pb, 256>>>(gabase, f0base, f1base, gbbase, dinv, rs, csr, n);
    prop2h_k<<<pb, 256>>>(gbbase, f1base, f0base, dinv, rs, csr, out, n);
    tail_k<<<(n + 31) / 32, 256>>>(out, weff, bm1, Wm2, bm2, logits, n);
}